// round 3
// baseline (speedup 1.0000x reference)
#include <cuda_runtime.h>
#include <math.h>

#define HID   256
#define NB    128
#define HW    32
#define GATES 1024        // 4*HID
#define BT    16          // batches per block
#define SH_PITCH 20       // padded pitch for transposed hsum tile (floats)

// Transposed recurrent weights: wT[k][row], 256 x 1024 (1 MB), for coalesced loads.
__device__ float g_wT[HID * GATES];
// Cell state for every grid cell: [cell][b][j].  32*32*128*256 floats = 134 MB.
__device__ float g_s[(size_t)HW * HW * NB * HID];

__global__ void transpose_w_kernel(const float* __restrict__ w_hh) {
    int idx = blockIdx.x * blockDim.x + threadIdx.x;   // over 1024*256
    if (idx < GATES * HID) {
        int row = idx >> 8;       // gate-output row 0..1023
        int k   = idx & (HID - 1);
        g_wT[k * GATES + row] = w_hh[idx];             // coalesced read
    }
}

__device__ __forceinline__ float sigmoidf_(float v) {
    return 1.0f / (1.0f + expf(-v));
}

// One anti-diagonal: all cells (r, c) with r + c == d.
// Block = 256 threads = one thread per hidden index j, covering BT=16 batches.
// gridDim.x = n_cells * (NB/BT).
__global__ __launch_bounds__(256, 2)
void diag_kernel(const float* __restrict__ x,
                 const float* __restrict__ w_ih,
                 const float* __restrict__ bias,
                 float*       __restrict__ out,   // h lives directly in the output tensor
                 int d)
{
    const int r0   = (d > HW - 1) ? d - (HW - 1) : 0;
    const int cell = blockIdx.x >> 3;            // / (NB/BT)
    const int bt   = blockIdx.x & 7;
    const int r    = r0 + cell;
    const int c    = d - r;
    const int j    = threadIdx.x;                // hidden index
    const int b0   = bt * BT;

    __shared__ float sh[HID][SH_PITCH];          // hsum tile, transposed: sh[k][bb]

    const size_t img     = (size_t)HW * HW * HID;   // per-batch h stride (262144)
    const int    cell_id = r * HW + c;

    // ---- Stage hsum = h_up + h_left into shared (transposed) ----
    #pragma unroll
    for (int bb = 0; bb < BT; bb++) {
        const int b = b0 + bb;
        const float* ob = out + (size_t)b * img;
        float hu = (r > 0) ? ob[(size_t)(cell_id - HW) * HID + j] : 0.0f;
        float hl = (c > 0) ? ob[(size_t)(cell_id - 1)  * HID + j] : 0.0f;
        sh[j][bb] = hu + hl;
    }
    __syncthreads();

    // ---- GEMM: gates[b][g*256+j] = sum_k hsum[b][k] * w_hh[g*256+j][k] ----
    float acc0[BT], acc1[BT], acc2[BT], acc3[BT];
    #pragma unroll
    for (int bb = 0; bb < BT; bb++) { acc0[bb]=0.f; acc1[bb]=0.f; acc2[bb]=0.f; acc3[bb]=0.f; }

    #pragma unroll 2
    for (int k = 0; k < HID; k++) {
        const float* wrow = g_wT + (size_t)k * GATES;
        const float w0 = wrow[j];
        const float w1 = wrow[HID     + j];
        const float w2 = wrow[2*HID   + j];
        const float w3 = wrow[3*HID   + j];
        const float4* shk = (const float4*)(&sh[k][0]);   // pitch 20 floats = 80 B, 16B aligned
        #pragma unroll
        for (int q = 0; q < BT / 4; q++) {
            const float4 hv4 = shk[q];                    // broadcast LDS.128
            const float hv[4] = {hv4.x, hv4.y, hv4.z, hv4.w};
            #pragma unroll
            for (int t = 0; t < 4; t++) {
                const int bb = q * 4 + t;
                acc0[bb] += w0 * hv[t];
                acc1[bb] += w1 * hv[t];
                acc2[bb] += w2 * hv[t];
                acc3[bb] += w3 * hv[t];
            }
        }
    }

    // ---- Cell epilogue ----
    const float bias0 = bias[j],        bias1 = bias[HID + j];
    const float bias2 = bias[2*HID + j], bias3 = bias[3*HID + j];
    const float wih0  = w_ih[j],        wih1  = w_ih[HID + j];
    const float wih2  = w_ih[2*HID + j], wih3  = w_ih[3*HID + j];

    const size_t sc_cur  = (size_t)cell_id        * NB * HID;
    const size_t sc_up   = (size_t)(cell_id - HW) * NB * HID;
    const size_t sc_left = (size_t)(cell_id - 1)  * NB * HID;

    #pragma unroll 4
    for (int bb = 0; bb < BT; bb++) {
        const int b = b0 + bb;
        const float xp = x[b * (HW * HW) + cell_id];

        const float gi = acc0[bb] + bias0 + xp * wih0;
        const float gf = acc1[bb] + bias1 + xp * wih1;
        const float gg = acc2[bb] + bias2 + xp * wih2;
        const float go = acc3[bb] + bias3 + xp * wih3;

        const float iv = sigmoidf_(gi);
        const float fv = sigmoidf_(gf);
        const float gv = tanhf(gg);
        const float ov = sigmoidf_(go);

        const float su = (r > 0) ? g_s[sc_up   + (size_t)b * HID + j] : 0.0f;
        const float sl = (c > 0) ? g_s[sc_left + (size_t)b * HID + j] : 0.0f;

        const float sv = fv * (su + sl) + iv * gv;
        const float hv = ov * tanhf(sv);

        g_s[sc_cur + (size_t)b * HID + j] = sv;
        out[(size_t)b * img + (size_t)cell_id * HID + j] = hv;
    }
}

extern "C" void kernel_launch(void* const* d_in, const int* in_sizes, int n_in,
                              void* d_out, int out_size) {
    const float* x    = (const float*)d_in[0];
    const float* w_ih = (const float*)d_in[1];
    const float* w_hh = (const float*)d_in[2];
    const float* bias = (const float*)d_in[3];
    float* out = (float*)d_out;

    transpose_w_kernel<<<(GATES * HID + 255) / 256, 256>>>(w_hh);

    for (int d = 0; d < 2 * HW - 1; d++) {
        const int n_d = (d < HW) ? (d + 1) : (2 * HW - 1 - d);
        diag_kernel<<<n_d * (NB / BT), 256>>>(x, w_ih, bias, out, d);
    }
}

// round 5
// speedup vs baseline: 1.2458x; 1.2458x over previous
#include <cuda_runtime.h>
#include <math.h>

#define HID   256
#define NB    128
#define HW    32
#define GATES 1024            // 4*HID
#define SH_PITCH 132          // floats per k-row in smem (128 + 4 pad; 528 B, 16B aligned)
#define THREADS 512           // 16 batch-groups x 32 j
#define JB    32              // j per block
#define SMEM_BYTES (HID * SH_PITCH * 4)   // 135168

// Repacked recurrent weights: wT2[k][j] = float4{w_i, w_f, w_g, w_o}, 1 MB.
__device__ float4 g_wT2[HID * HID];
// Cell state: [cell][b][j]. 32*32*128*256 floats = 134 MB.
__device__ float g_s[(size_t)HW * HW * NB * HID];

__global__ void transpose_w_kernel(const float* __restrict__ w_hh) {
    int idx = blockIdx.x * blockDim.x + threadIdx.x;   // over 4*256*256
    if (idx < GATES * HID) {
        // coalesced read: idx = row*256 + k, row = type*256 + j
        int k    = idx & (HID - 1);
        int row  = idx >> 8;
        int type = row >> 8;
        int j    = row & (HID - 1);
        ((float*)g_wT2)[4 * (k * HID + j) + type] = w_hh[idx];
    }
}

__device__ __forceinline__ float sigmoidf_(float v) {
    return 1.0f / (1.0f + expf(-v));
}

__device__ __forceinline__ unsigned long long dup_f32x2(float w) {
    unsigned long long r;
    asm("mov.b64 %0, {%1, %1};" : "=l"(r) : "f"(w));
    return r;
}

__device__ __forceinline__ void fma_f32x2(unsigned long long& acc,
                                          unsigned long long a,
                                          unsigned long long b) {
    asm("fma.rn.f32x2 %0, %1, %2, %0;" : "+l"(acc) : "l"(a), "l"(b));
}

// One anti-diagonal. Block = 512 threads = 16 batch-groups x 32 j.
// Block tile: 32 j (all 4 gate types) x 128 batches. gridDim.x = n_cells * 8.
__global__ __launch_bounds__(THREADS, 1)
void diag_kernel(const float* __restrict__ x,
                 const float* __restrict__ w_ih,
                 const float* __restrict__ bias,
                 float*       __restrict__ out,
                 int d)
{
    extern __shared__ float sh[];                 // sh[k*SH_PITCH + b] = h_up+h_left

    const int r0      = (d > HW - 1) ? d - (HW - 1) : 0;
    const int cell    = blockIdx.x >> 3;
    const int jb      = blockIdx.x & 7;
    const int r       = r0 + cell;
    const int c       = d - r;
    const int cell_id = r * HW + c;

    const int t  = threadIdx.x;
    const int jt = t & (JB - 1);
    const int bg = t >> 5;                        // 0..15
    const int j  = jb * JB + jt;
    const int b0 = bg * 8;

    const size_t img = (size_t)HW * HW * HID;     // per-batch h stride

    // ---- Stage hsum = h_up + h_left into smem, layout [k][b] ----
    const size_t up_off   = (size_t)(cell_id - HW) * HID;
    const size_t left_off = (size_t)(cell_id - 1)  * HID;
    #pragma unroll 4
    for (int it = 0; it < (NB * HID) / THREADS; it++) {
        const int idx = it * THREADS + t;
        const int b = idx >> 8;
        const int k = idx & (HID - 1);
        const size_t boff = (size_t)b * img;
        float v = 0.0f;
        if (r > 0) v += out[boff + up_off + k];
        if (c > 0) v += out[boff + left_off + k];
        sh[k * SH_PITCH + b] = v;
    }
    __syncthreads();

    // ---- GEMM: 16 f32x2 accumulators = 4 gate types x 4 batch-pairs ----
    unsigned long long acc[16];
    #pragma unroll
    for (int q = 0; q < 16; q++) acc[q] = 0ull;

    const float4* __restrict__ wv = g_wT2;

    #pragma unroll 4
    for (int k = 0; k < HID; k++) {
        const float4 w4 = __ldg(&wv[k * HID + j]);          // LDG.128, coalesced
        const float* shk = &sh[k * SH_PITCH + b0];
        const ulonglong2 hA = *(const ulonglong2*)(shk);     // batch pairs 0,1 (broadcast)
        const ulonglong2 hB = *(const ulonglong2*)(shk + 4); // batch pairs 2,3

        const unsigned long long w2i = dup_f32x2(w4.x);
        const unsigned long long w2f = dup_f32x2(w4.y);
        const unsigned long long w2g = dup_f32x2(w4.z);
        const unsigned long long w2o = dup_f32x2(w4.w);

        fma_f32x2(acc[ 0], hA.x, w2i);  fma_f32x2(acc[ 1], hA.y, w2i);
        fma_f32x2(acc[ 2], hB.x, w2i);  fma_f32x2(acc[ 3], hB.y, w2i);
        fma_f32x2(acc[ 4], hA.x, w2f);  fma_f32x2(acc[ 5], hA.y, w2f);
        fma_f32x2(acc[ 6], hB.x, w2f);  fma_f32x2(acc[ 7], hB.y, w2f);
        fma_f32x2(acc[ 8], hA.x, w2g);  fma_f32x2(acc[ 9], hA.y, w2g);
        fma_f32x2(acc[10], hB.x, w2g);  fma_f32x2(acc[11], hB.y, w2g);
        fma_f32x2(acc[12], hA.x, w2o);  fma_f32x2(acc[13], hA.y, w2o);
        fma_f32x2(acc[14], hB.x, w2o);  fma_f32x2(acc[15], hB.y, w2o);
    }

    // ---- Cell epilogue (thread-local: owns all 4 gate types of its j) ----
    const float bias0 = bias[j],           bias1 = bias[HID + j];
    const float bias2 = bias[2 * HID + j], bias3 = bias[3 * HID + j];
    const float wih0  = w_ih[j],           wih1  = w_ih[HID + j];
    const float wih2  = w_ih[2 * HID + j], wih3  = w_ih[3 * HID + j];

    const size_t sc_cur  = (size_t)cell_id        * NB * HID;
    const size_t sc_up   = (size_t)(cell_id - HW) * NB * HID;
    const size_t sc_left = (size_t)(cell_id - 1)  * NB * HID;

    #pragma unroll
    for (int bb = 0; bb < 8; bb++) {
        const int b    = b0 + bb;
        const int p    = bb >> 1;
        const int half = bb & 1;

        float a0, a1, a2, a3;
        {
            const uint2 u0 = *(const uint2*)&acc[ 0 + p];
            const uint2 u1 = *(const uint2*)&acc[ 4 + p];
            const uint2 u2 = *(const uint2*)&acc[ 8 + p];
            const uint2 u3 = *(const uint2*)&acc[12 + p];
            a0 = __uint_as_float(half ? u0.y : u0.x);
            a1 = __uint_as_float(half ? u1.y : u1.x);
            a2 = __uint_as_float(half ? u2.y : u2.x);
            a3 = __uint_as_float(half ? u3.y : u3.x);
        }

        const float xp = x[b * (HW * HW) + cell_id];

        const float gi = a0 + bias0 + xp * wih0;
        const float gf = a1 + bias1 + xp * wih1;
        const float gg = a2 + bias2 + xp * wih2;
        const float go = a3 + bias3 + xp * wih3;

        const float iv = sigmoidf_(gi);
        const float fv = sigmoidf_(gf);
        const float gv = tanhf(gg);
        const float ov = sigmoidf_(go);

        float ssum = 0.0f;
        if (r > 0) ssum += g_s[sc_up   + (size_t)b * HID + j];
        if (c > 0) ssum += g_s[sc_left + (size_t)b * HID + j];

        const float sv = fv * ssum + iv * gv;
        const float hv = ov * tanhf(sv);

        g_s[sc_cur + (size_t)b * HID + j] = sv;
        out[(size_t)b * img + (size_t)cell_id * HID + j] = hv;
    }
}

extern "C" void kernel_launch(void* const* d_in, const int* in_sizes, int n_in,
                              void* d_out, int out_size) {
    const float* x    = (const float*)d_in[0];
    const float* w_ih = (const float*)d_in[1];
    const float* w_hh = (const float*)d_in[2];
    const float* bias = (const float*)d_in[3];
    float* out = (float*)d_out;

    cudaFuncSetAttribute(diag_kernel,
                         cudaFuncAttributeMaxDynamicSharedMemorySize, SMEM_BYTES);

    transpose_w_kernel<<<(GATES * HID + 255) / 256, 256>>>(w_hh);

    for (int d = 0; d < 2 * HW - 1; d++) {
        const int n_d = (d < HW) ? (d + 1) : (2 * HW - 1 - d);
        diag_kernel<<<n_d * 8, THREADS, SMEM_BYTES>>>(x, w_ih, bias, out, d);
    }
}

// round 6
// speedup vs baseline: 1.2697x; 1.0192x over previous
#include <cuda_runtime.h>
#include <math.h>

#define HID   256
#define NB    128
#define HW    32
#define GATES 1024            // 4*HID
#define SH_PITCH 132          // floats per k-row in smem (128 + 4 pad)
#define THREADS 512           // 16 batch-groups x 32 j
#define JB    32              // j per block
#define SMEM_BYTES (HID * SH_PITCH * 4)   // 135168
#define NBLK   144            // persistent blocks = CSLOTS * 8
#define CSLOTS 18

// Repacked recurrent weights: wT2[k][j] = float4{w_i, w_f, w_g, w_o}, 1 MB.
__device__ float4 g_wT2[HID * HID];
// Cell state: [cell][b][j]. 134 MB scratch.
__device__ float g_s[(size_t)HW * HW * NB * HID];
// Software global barrier state (count returns to 0 after each barrier).
__device__ int      g_bar_count;
__device__ unsigned g_bar_gen;

__global__ void transpose_w_kernel(const float* __restrict__ w_hh) {
    int idx = blockIdx.x * blockDim.x + threadIdx.x;   // over 4*256*256
    if (idx < GATES * HID) {
        int k    = idx & (HID - 1);
        int row  = idx >> 8;
        int type = row >> 8;
        int j    = row & (HID - 1);
        ((float*)g_wT2)[4 * (k * HID + j) + type] = w_hh[idx];
    }
}

__device__ __forceinline__ float sigmoidf_(float v) {
    return 1.0f / (1.0f + expf(-v));
}

__device__ __forceinline__ unsigned long long dup_f32x2(float w) {
    unsigned long long r;
    asm("mov.b64 %0, {%1, %1};" : "=l"(r) : "f"(w));
    return r;
}

__device__ __forceinline__ void fma_f32x2(unsigned long long& acc,
                                          unsigned long long a,
                                          unsigned long long b) {
    asm("fma.rn.f32x2 %0, %1, %2, %0;" : "+l"(acc) : "l"(a), "l"(b));
}

// Chip-wide barrier: all NBLK blocks arrive; thread 0 spins, rest park on BAR.
__device__ __forceinline__ void grid_barrier() {
    __syncthreads();
    if (threadIdx.x == 0) {
        __threadfence();                      // make out/g_s stores visible
        unsigned gen = *((volatile unsigned*)&g_bar_gen);
        int t = atomicAdd(&g_bar_count, 1);
        if (t == NBLK - 1) {
            g_bar_count = 0;
            __threadfence();
            atomicAdd(&g_bar_gen, 1u);        // release
        } else {
            while (*((volatile unsigned*)&g_bar_gen) == gen) { }
        }
    }
    __syncthreads();
}

// Persistent kernel: one launch walks all 63 anti-diagonals.
// Block = 512 threads = 16 batch-groups x 32 j. bid = cslot*8 + jb (jb fixed
// per block so its 128 KB w-slice stays L1-resident across all diagonals).
__global__ __launch_bounds__(THREADS, 1)
void mdlstm_persistent(const float* __restrict__ x,
                       const float* __restrict__ w_ih,
                       const float* __restrict__ bias,
                       float*       __restrict__ out)
{
    extern __shared__ float sh[];             // sh[k*SH_PITCH + b] = h_up+h_left

    const int bid   = blockIdx.x;
    const int jb    = bid & 7;
    const int cslot = bid >> 3;               // 0..17

    const int t  = threadIdx.x;
    const int jt = t & (JB - 1);
    const int bg = t >> 5;                    // 0..15
    const int j  = jb * JB + jt;
    const int b0 = bg * 8;

    const size_t img = (size_t)HW * HW * HID; // per-batch h stride

    // Hoisted per-j constants (L1/const-cached, loop-invariant).
    const float bias0 = bias[j],           bias1 = bias[HID + j];
    const float bias2 = bias[2 * HID + j], bias3 = bias[3 * HID + j];
    const float wih0  = w_ih[j],           wih1  = w_ih[HID + j];
    const float wih2  = w_ih[2 * HID + j], wih3  = w_ih[3 * HID + j];

    for (int d = 0; d < 2 * HW - 1; d++) {
        const int n_d = (d < HW) ? (d + 1) : (2 * HW - 1 - d);
        const int r0  = (d > HW - 1) ? d - (HW - 1) : 0;

        for (int cell = cslot; cell < n_d; cell += CSLOTS) {
            const int r       = r0 + cell;
            const int c       = d - r;
            const int cell_id = r * HW + c;

            // ---- Stage hsum = h_up + h_left into smem, layout [k][b] ----
            const size_t up_off   = (size_t)(cell_id - HW) * HID;
            const size_t left_off = (size_t)(cell_id - 1)  * HID;
            #pragma unroll 4
            for (int it = 0; it < (NB * HID) / THREADS; it++) {
                const int idx = it * THREADS + t;
                const int b = idx >> 8;
                const int k = idx & (HID - 1);
                const size_t boff = (size_t)b * img;
                float v = 0.0f;
                if (r > 0) v += out[boff + up_off + k];
                if (c > 0) v += out[boff + left_off + k];
                sh[k * SH_PITCH + b] = v;
            }
            __syncthreads();

            // ---- GEMM: 16 f32x2 accumulators = 4 gates x 4 batch-pairs ----
            unsigned long long acc[16];
            #pragma unroll
            for (int q = 0; q < 16; q++) acc[q] = 0ull;

            const float4* __restrict__ wv = g_wT2;

            #pragma unroll 4
            for (int k = 0; k < HID; k++) {
                const float4 w4 = __ldg(&wv[k * HID + j]);   // L1-resident slice
                const float* shk = &sh[k * SH_PITCH + b0];
                const ulonglong2 hA = *(const ulonglong2*)(shk);
                const ulonglong2 hB = *(const ulonglong2*)(shk + 4);

                const unsigned long long w2i = dup_f32x2(w4.x);
                const unsigned long long w2f = dup_f32x2(w4.y);
                const unsigned long long w2g = dup_f32x2(w4.z);
                const unsigned long long w2o = dup_f32x2(w4.w);

                fma_f32x2(acc[ 0], hA.x, w2i);  fma_f32x2(acc[ 1], hA.y, w2i);
                fma_f32x2(acc[ 2], hB.x, w2i);  fma_f32x2(acc[ 3], hB.y, w2i);
                fma_f32x2(acc[ 4], hA.x, w2f);  fma_f32x2(acc[ 5], hA.y, w2f);
                fma_f32x2(acc[ 6], hB.x, w2f);  fma_f32x2(acc[ 7], hB.y, w2f);
                fma_f32x2(acc[ 8], hA.x, w2g);  fma_f32x2(acc[ 9], hA.y, w2g);
                fma_f32x2(acc[10], hB.x, w2g);  fma_f32x2(acc[11], hB.y, w2g);
                fma_f32x2(acc[12], hA.x, w2o);  fma_f32x2(acc[13], hA.y, w2o);
                fma_f32x2(acc[14], hB.x, w2o);  fma_f32x2(acc[15], hB.y, w2o);
            }

            // ---- Cell epilogue ----
            const size_t sc_cur  = (size_t)cell_id        * NB * HID;
            const size_t sc_up   = (size_t)(cell_id - HW) * NB * HID;
            const size_t sc_left = (size_t)(cell_id - 1)  * NB * HID;

            #pragma unroll
            for (int bb = 0; bb < 8; bb++) {
                const int b    = b0 + bb;
                const int p    = bb >> 1;
                const int half = bb & 1;

                float a0, a1, a2, a3;
                {
                    const uint2 u0 = *(const uint2*)&acc[ 0 + p];
                    const uint2 u1 = *(const uint2*)&acc[ 4 + p];
                    const uint2 u2 = *(const uint2*)&acc[ 8 + p];
                    const uint2 u3 = *(const uint2*)&acc[12 + p];
                    a0 = __uint_as_float(half ? u0.y : u0.x);
                    a1 = __uint_as_float(half ? u1.y : u1.x);
                    a2 = __uint_as_float(half ? u2.y : u2.x);
                    a3 = __uint_as_float(half ? u3.y : u3.x);
                }

                const float xp = x[b * (HW * HW) + cell_id];

                const float gi = a0 + bias0 + xp * wih0;
                const float gf = a1 + bias1 + xp * wih1;
                const float gg = a2 + bias2 + xp * wih2;
                const float go = a3 + bias3 + xp * wih3;

                const float iv = sigmoidf_(gi);
                const float fv = sigmoidf_(gf);
                const float gv = tanhf(gg);
                const float ov = sigmoidf_(go);

                float ssum = 0.0f;
                if (r > 0) ssum += g_s[sc_up   + (size_t)b * HID + j];
                if (c > 0) ssum += g_s[sc_left + (size_t)b * HID + j];

                const float sv = fv * ssum + iv * gv;
                const float hv = ov * tanhf(sv);

                g_s[sc_cur + (size_t)b * HID + j] = sv;
                out[(size_t)b * img + (size_t)cell_id * HID + j] = hv;
            }
            __syncthreads();   // protect sh before next cell's staging
        }

        grid_barrier();        // diagonal d complete chip-wide
    }
}

extern "C" void kernel_launch(void* const* d_in, const int* in_sizes, int n_in,
                              void* d_out, int out_size) {
    const float* x    = (const float*)d_in[0];
    const float* w_ih = (const float*)d_in[1];
    const float* w_hh = (const float*)d_in[2];
    const float* bias = (const float*)d_in[3];
    float* out = (float*)d_out;

    cudaFuncSetAttribute(mdlstm_persistent,
                         cudaFuncAttributeMaxDynamicSharedMemorySize, SMEM_BYTES);

    transpose_w_kernel<<<(GATES * HID + 255) / 256, 256>>>(w_hh);
    mdlstm_persistent<<<NBLK, THREADS, SMEM_BYTES>>>(x, w_ih, bias, out);
}

// round 8
// speedup vs baseline: 1.5557x; 1.2252x over previous
#include <cuda_runtime.h>
#include <cuda_bf16.h>
#include <math.h>
#include <stdint.h>

#define HID   256
#define NB    128
#define HW    32
#define NBLK  144            // 9 cell-slots x 16 j-slices, persistent (1/SM)
#define CSLOTS 9
#define THREADS 256
#define PITCH 528            // bytes per bf16 tile row (264 bf16; 33x16B -> ldmatrix conflict-free)

// ---- smem layout (bytes) ----
#define SM_CONST 0                              // bias[64], wih[64] floats (512 B)
#define SM_A_HI  1024                           // A hi: 128 x 264 bf16 (67584 B)
#define SM_A_LO  (SM_A_HI + 128 * PITCH)
#define SM_W_HI  (SM_A_LO + 128 * PITCH)        // W hi: 64 x 264 bf16 (33792 B)
#define SM_W_LO  (SM_W_HI + 64 * PITCH)
#define SMEM_TOTAL (SM_W_LO + 64 * PITCH)       // 203776 B

// Cell state s, layout [cell][b][j]. 134 MB scratch.
__device__ float g_s[(size_t)HW * HW * NB * HID];
// grid barrier
__device__ int      g_bar_count;
__device__ unsigned g_bar_gen;

__device__ __forceinline__ uint32_t smem_u32(const void* p) {
    uint32_t a;
    asm("{ .reg .u64 t; cvta.to.shared.u64 t, %1; cvt.u32.u64 %0, t; }" : "=r"(a) : "l"(p));
    return a;
}
__device__ __forceinline__ float sigmoidf_(float v) { return 1.0f / (1.0f + expf(-v)); }

__device__ __forceinline__ void ldm_x4(uint32_t& r0, uint32_t& r1, uint32_t& r2, uint32_t& r3,
                                       uint32_t addr) {
    asm volatile("ldmatrix.sync.aligned.m8n8.x4.shared.b16 {%0,%1,%2,%3}, [%4];"
        : "=r"(r0), "=r"(r1), "=r"(r2), "=r"(r3) : "r"(addr));
}
__device__ __forceinline__ void mma_bf16(float* c, const uint32_t* a, uint32_t b0, uint32_t b1) {
    asm volatile(
        "mma.sync.aligned.m16n8k16.row.col.f32.bf16.bf16.f32 "
        "{%0,%1,%2,%3}, {%4,%5,%6,%7}, {%8,%9}, {%0,%1,%2,%3};"
        : "+f"(c[0]), "+f"(c[1]), "+f"(c[2]), "+f"(c[3])
        : "r"(a[0]), "r"(a[1]), "r"(a[2]), "r"(a[3]), "r"(b0), "r"(b1));
}

__device__ __forceinline__ uint32_t bf2u(__nv_bfloat162 v) {
    return *reinterpret_cast<uint32_t*>(&v);
}
// split float pair -> (hi bf16x2, lo bf16x2)
__device__ __forceinline__ void split2(float a, float b, uint32_t& hi, uint32_t& lo) {
    __nv_bfloat162 h = __floats2bfloat162_rn(a, b);
    float la = a - __low2float(h);
    float lb = b - __high2float(h);
    __nv_bfloat162 l = __floats2bfloat162_rn(la, lb);
    hi = bf2u(h); lo = bf2u(l);
}

__device__ __forceinline__ void grid_barrier() {
    __syncthreads();
    if (threadIdx.x == 0) {
        __threadfence();
        unsigned gen = *((volatile unsigned*)&g_bar_gen);
        int t = atomicAdd(&g_bar_count, 1);
        if (t == NBLK - 1) {
            g_bar_count = 0;
            __threadfence();
            atomicAdd(&g_bar_gen, 1u);
        } else {
            while (*((volatile unsigned*)&g_bar_gen) == gen) { }
        }
    }
    __syncthreads();
}

// Persistent MD-LSTM: one launch walks all 63 anti-diagonals.
// Block = 256 threads (8 warps). Tile: M=128 batches x N=64 gate rows
// (n = type*16 + jt; j = sb*16 + jt) x K=256, split-precision bf16 HMMA.
__global__ __launch_bounds__(THREADS, 1)
void mdlstm_mma(const float* __restrict__ x,
                const float* __restrict__ w_ih,
                const float* __restrict__ w_hh,
                const float* __restrict__ bias,
                float*       __restrict__ out)
{
    extern __shared__ unsigned char smem[];
    const uint32_t smb  = smem_u32(smem);
    const int tid  = threadIdx.x;
    const int lane = tid & 31;
    const int wrp  = tid >> 5;            // 0..7
    const int sb    = blockIdx.x & 15;    // j-slice
    const int cslot = blockIdx.x >> 4;    // 0..8

    // ---- one-time: W slice (64 rows x 256 k) split into smem hi/lo ----
    {
        const int n    = tid >> 2;                 // 0..63
        const int kc   = (tid & 3) * 64;
        const int type = n >> 4, jt = n & 15;
        const int j    = sb * 16 + jt;
        const float* src = w_hh + ((size_t)(type * 256 + j) * 256 + kc);
        unsigned char* dhi = smem + SM_W_HI + n * PITCH + kc * 2;
        unsigned char* dlo = smem + SM_W_LO + n * PITCH + kc * 2;
        #pragma unroll 4
        for (int i = 0; i < 16; i++) {
            float4 v = *(const float4*)(src + i * 4);
            uint32_t h0, l0, h1, l1;
            split2(v.x, v.y, h0, l0);
            split2(v.z, v.w, h1, l1);
            *(uint2*)(dhi + i * 8) = make_uint2(h0, h1);
            *(uint2*)(dlo + i * 8) = make_uint2(l0, l1);
        }
    }
    if (tid < 64) {
        const int type = tid >> 4, jt = tid & 15;
        const int j = sb * 16 + jt;
        ((float*)(smem + SM_CONST))[tid]      = bias[type * 256 + j];
        ((float*)(smem + SM_CONST))[64 + tid] = w_ih[type * 256 + j];
    }
    __syncthreads();

    // per-lane ldmatrix address components
    const int m0 = wrp * 16;
    const uint32_t a_off = (uint32_t)(m0 + (lane & 15)) * PITCH + (lane >> 4) * 16;
    const uint32_t b_off = (uint32_t)(lane & 15) * PITCH + (lane >> 4) * 16;

    const int q  = lane & 3;
    const int g8 = lane >> 2;
    const float* sbias = (const float*)(smem + SM_CONST);
    const float* swih  = sbias + 64;

    for (int d = 0; d < 2 * HW - 1; d++) {
        const int n_d = (d < HW) ? (d + 1) : (2 * HW - 1 - d);
        const int r0  = (d > HW - 1) ? d - (HW - 1) : 0;

        for (int cell = cslot; cell < n_d; cell += CSLOTS) {
            const int r = r0 + cell, c = d - r;
            const int cell_id = r * HW + c;
            const bool has_up = (r > 0), has_left = (c > 0);

            float acc[8][4];
            #pragma unroll
            for (int f = 0; f < 8; f++)
                #pragma unroll
                for (int e = 0; e < 4; e++) acc[f][e] = 0.0f;

            if (has_up || has_left) {
                // ---- stage hsum = h_up + h_left, split -> smem A hi/lo ----
                {
                    const int bb = tid >> 1;
                    const int j0 = (tid & 1) * 128;
                    const float* pu = out + (size_t)bb * (HW * HW * HID)
                                          + (size_t)(cell_id - HW) * HID + j0;
                    const float* pl = out + (size_t)bb * (HW * HW * HID)
                                          + (size_t)(cell_id - 1) * HID + j0;
                    unsigned char* ahi = smem + SM_A_HI + bb * PITCH + j0 * 2;
                    unsigned char* alo = smem + SM_A_LO + bb * PITCH + j0 * 2;
                    #pragma unroll 8
                    for (int i = 0; i < 32; i++) {
                        float4 v = make_float4(0.f, 0.f, 0.f, 0.f);
                        if (has_up) {
                            float4 u = *(const float4*)(pu + i * 4);
                            v.x = u.x; v.y = u.y; v.z = u.z; v.w = u.w;
                        }
                        if (has_left) {
                            float4 l = *(const float4*)(pl + i * 4);
                            v.x += l.x; v.y += l.y; v.z += l.z; v.w += l.w;
                        }
                        uint32_t h0, l0, h1, l1;
                        split2(v.x, v.y, h0, l0);
                        split2(v.z, v.w, h1, l1);
                        *(uint2*)(ahi + i * 8) = make_uint2(h0, h1);
                        *(uint2*)(alo + i * 8) = make_uint2(l0, l1);
                    }
                }
                __syncthreads();

                // ---- GEMM: gates[b][n] = sum_k hsum[b][k] * W[n][k] ----
                #pragma unroll 2
                for (int kk = 0; kk < 16; kk++) {
                    const uint32_t ka = kk * 32;        // 16 bf16 = 32 B per k-step
                    uint32_t ah[4], al[4];
                    ldm_x4(ah[0], ah[1], ah[2], ah[3], smb + SM_A_HI + a_off + ka);
                    ldm_x4(al[0], al[1], al[2], al[3], smb + SM_A_LO + a_off + ka);
                    #pragma unroll
                    for (int g = 0; g < 4; g++) {
                        uint32_t bh0, bh1, bh2, bh3, bl0, bl1, bl2, bl3;
                        ldm_x4(bh0, bh1, bh2, bh3,
                               smb + SM_W_HI + (uint32_t)g * 16 * PITCH + b_off + ka);
                        ldm_x4(bl0, bl1, bl2, bl3,
                               smb + SM_W_LO + (uint32_t)g * 16 * PITCH + b_off + ka);
                        mma_bf16(acc[g * 2],     ah, bh0, bh2);
                        mma_bf16(acc[g * 2 + 1], ah, bh1, bh3);
                        mma_bf16(acc[g * 2],     ah, bl0, bl2);
                        mma_bf16(acc[g * 2 + 1], ah, bl1, bl3);
                        mma_bf16(acc[g * 2],     al, bh0, bh2);
                        mma_bf16(acc[g * 2 + 1], al, bh1, bh3);
                    }
                }
            }

            // ---- epilogue: thread owns (2 b-rows) x (4 jt) x 4 gate types ----
            const size_t s_cur  = (size_t)cell_id * NB * HID;
            const size_t s_up   = (size_t)(cell_id - HW) * NB * HID;
            const size_t s_left = (size_t)(cell_id - 1) * NB * HID;

            #pragma unroll
            for (int h = 0; h < 2; h++) {
                const int b = m0 + g8 + h * 8;
                const float xp = x[b * (HW * HW) + cell_id];
                #pragma unroll
                for (int p = 0; p < 2; p++) {
                    const int jt0 = p * 8 + q * 2;
                    const int j0e = sb * 16 + jt0;

                    float2 ssum = make_float2(0.f, 0.f);
                    if (has_up) {
                        float2 t = *(const float2*)&g_s[s_up + (size_t)b * HID + j0e];
                        ssum.x += t.x; ssum.y += t.y;
                    }
                    if (has_left) {
                        float2 t = *(const float2*)&g_s[s_left + (size_t)b * HID + j0e];
                        ssum.x += t.x; ssum.y += t.y;
                    }

                    float sv[2], hv[2];
                    #pragma unroll
                    for (int cc = 0; cc < 2; cc++) {
                        const int jt = jt0 + cc;
                        const int e  = h * 2 + cc;
                        const float gi = acc[0 + p][e] + sbias[jt]      + xp * swih[jt];
                        const float gf = acc[2 + p][e] + sbias[16 + jt] + xp * swih[16 + jt];
                        const float gg = acc[4 + p][e] + sbias[32 + jt] + xp * swih[32 + jt];
                        const float go = acc[6 + p][e] + sbias[48 + jt] + xp * swih[48 + jt];

                        const float iv = sigmoidf_(gi);
                        const float fv = sigmoidf_(gf);
                        const float gv = tanhf(gg);
                        const float ov = sigmoidf_(go);

                        const float ss = (cc == 0) ? ssum.x : ssum.y;
                        sv[cc] = fv * ss + iv * gv;
                        hv[cc] = ov * tanhf(sv[cc]);
                    }
                    *(float2*)&g_s[s_cur + (size_t)b * HID + j0e] = make_float2(sv[0], sv[1]);
                    *(float2*)&out[(size_t)b * (HW * HW * HID)
                                   + (size_t)cell_id * HID + j0e]  = make_float2(hv[0], hv[1]);
                }
            }
            __syncthreads();   // all warps done with smem A before next staging
        }
        grid_barrier();
    }
}

extern "C" void kernel_launch(void* const* d_in, const int* in_sizes, int n_in,
                              void* d_out, int out_size) {
    const float* x    = (const float*)d_in[0];
    const float* w_ih = (const float*)d_in[1];
    const float* w_hh = (const float*)d_in[2];
    const float* bias = (const float*)d_in[3];
    float* out = (float*)d_out;

    cudaFuncSetAttribute(mdlstm_mma,
                         cudaFuncAttributeMaxDynamicSharedMemorySize, SMEM_TOTAL);
    mdlstm_mma<<<NBLK, THREADS, SMEM_TOTAL>>>(x, w_ih, w_hh, bias, out);
}